// round 15
// baseline (speedup 1.0000x reference)
#include <cuda_runtime.h>
#include <cuda_fp16.h>
#include <cstdint>

#define DIM     768
#define HEADS   12
#define HD      64
#define BATCH   4
#define SEQ     2048
#define M_TOTAL (BATCH * SEQ)

// Q prescale: 0.125 (attn scale) * log2(e), folded into Q so softmax is bare ex2
#define QSCALE  0.18033688011112042f

// Scratch (static device globals: allocation-guard safe)
__device__ __half g_xh[M_TOTAL * DIM];
__device__ __half g_wq[DIM * DIM], g_wk[DIM * DIM], g_wv[DIM * DIM], g_wp[DIM * DIM];
__device__ __half g_q[M_TOTAL * DIM], g_k[M_TOTAL * DIM];
__device__ __half g_v[M_TOTAL * DIM], g_o[M_TOTAL * DIM];

__device__ __forceinline__ uint32_t smem_u32(const void* p) {
    uint32_t a;
    asm("{ .reg .u64 t; cvta.to.shared.u64 t, %1; cvt.u32.u64 %0, t; }"
        : "=r"(a) : "l"(p));
    return a;
}
__device__ __forceinline__ float ex2f(float x) {
    float r;
    asm("ex2.approx.f32 %0, %1;" : "=f"(r) : "f"(x));
    return r;
}

#define CP16(dst, src) \
    asm volatile("cp.async.cg.shared.global [%0], [%1], 16;\n" :: "r"(dst), "l"(src))
#define CPC()  asm volatile("cp.async.commit_group;\n" ::: "memory")
#define CPW1() asm volatile("cp.async.wait_group 1;\n" ::: "memory")
#define CPW0() asm volatile("cp.async.wait_group 0;\n" ::: "memory")

#define LDSM4(r0, r1, r2, r3, a)                                              \
    asm volatile("ldmatrix.sync.aligned.m8n8.x4.shared.b16 {%0,%1,%2,%3}, [%4];" \
        : "=r"(r0), "=r"(r1), "=r"(r2), "=r"(r3) : "r"(a))
#define LDSM4T(r0, r1, r2, r3, a)                                             \
    asm volatile("ldmatrix.sync.aligned.m8n8.x4.trans.shared.b16 {%0,%1,%2,%3}, [%4];" \
        : "=r"(r0), "=r"(r1), "=r"(r2), "=r"(r3) : "r"(a))

// D += A(16x16,row) * B(16x8,col) — fp16 inputs, fp32 accum
#define MMA_F16(d, a0, a1, a2, a3, b0, b1)                                    \
    asm volatile("mma.sync.aligned.m16n8k16.row.col.f32.f16.f16.f32 "         \
        "{%0,%1,%2,%3}, {%4,%5,%6,%7}, {%8,%9}, {%0,%1,%2,%3};"               \
        : "+f"((d).x), "+f"((d).y), "+f"((d).z), "+f"((d).w)                  \
        : "r"(a0), "r"(a1), "r"(a2), "r"(a3), "r"(b0), "r"(b1))

// Swizzled byte address: 128B rows, 8 chunks of 16B, chunk key = row&7
__device__ __forceinline__ uint32_t swad(uint32_t base, int row, int chk) {
    return base + row * 128 + ((chk ^ (row & 7)) << 4);
}

// ---------------------------------------------------------------------------
// fp32 -> fp16 conversion: 32B of halves per thread-iter (uint4 stores)
// ---------------------------------------------------------------------------
__global__ void cvt_half(const float* __restrict__ x,  const float* __restrict__ wq,
                         const float* __restrict__ wk, const float* __restrict__ wv,
                         const float* __restrict__ wp)
{
    const int NX = M_TOTAL * DIM / 8;
    const int NW = DIM * DIM / 8;
    int stride = gridDim.x * blockDim.x;
    for (int u = blockIdx.x * blockDim.x + threadIdx.x; u < NX + 4 * NW; u += stride) {
        const float* src; __half* dst; int off;
        if (u < NX) { src = x; dst = g_xh; off = u; }
        else {
            int w = (u - NX) / NW, r = (u - NX) % NW;
            src = (w == 0) ? wq : (w == 1) ? wk : (w == 2) ? wv : wp;
            dst = (w == 0) ? g_wq : (w == 1) ? g_wk : (w == 2) ? g_wv : g_wp;
            off = r;
        }
        float4 f0 = ((const float4*)src)[off * 2 + 0];
        float4 f1 = ((const float4*)src)[off * 2 + 1];
        __half2 h[4];
        h[0] = __floats2half2_rn(f0.x, f0.y);
        h[1] = __floats2half2_rn(f0.z, f0.w);
        h[2] = __floats2half2_rn(f1.x, f1.y);
        h[3] = __floats2half2_rn(f1.z, f1.w);
        ((uint4*)dst)[off] = *(uint4*)h;
    }
}

// ---------------------------------------------------------------------------
// FUSED QKV GEMM: one pass over x computes Q, K, V.
// A (x) fragments loaded ONCE per kc and reused for all 3 weights ->
// LDS-bytes/MMA drops ~35% (the shared-pipe is the measured bottleneck).
// 256 threads, 8 warps (2x4), warp tile 64x32 per weight, BK=64.
// 3-slot ring of (A 16KB + B0..B2 16KB each) = 192KB -> 1 CTA/SM.
// All global pointers are __device__ symbols (no param regs).
// ---------------------------------------------------------------------------
__global__ void __launch_bounds__(256, 1) gemm_qkv3()
{
    extern __shared__ uint32_t smw[];   // 3 slots x 64KB

    const int tid = threadIdx.x, lane = tid & 31, warp = tid >> 5;
    const int wm = warp >> 2, wn = warp & 3;
    const int tg = lane & 3, gp = lane >> 2;
    const int l8 = lane & 7, lg = lane >> 3;
    const int bm = blockIdx.y * 128, bn = blockIdx.x * 128;
    const uint32_t base = smem_u32(smw);

    float4 acc[3][4][4];
    #pragma unroll
    for (int w = 0; w < 3; w++)
        #pragma unroll
        for (int i = 0; i < 4; i++)
            #pragma unroll
            for (int j = 0; j < 4; j++) acc[w][i][j] = make_float4(0.f, 0.f, 0.f, 0.f);

    const int arow = wm * 64 + l8 + ((lg & 1) << 3);
    const int achk = lg >> 1;
    const int brow = wn * 32 + l8 + ((lg >> 1) << 3);
    const int bchk = lg & 1;

#define Q3STAGE(SLOT, S) do {                                                  \
    int _k = (S) * 64;                                                         \
    uint32_t _ab = base + (SLOT) * 65536;                                      \
    _Pragma("unroll")                                                          \
    for (int _u = tid; _u < 1024; _u += 256) {                                 \
        int _r = _u >> 3, _g = _u & 7;                                         \
        uint32_t _d = _r * 128 + ((_g ^ (_r & 7)) << 4);                       \
        size_t _go = (size_t)(bm + _r) * DIM + _k + _g * 8;                    \
        size_t _wo = (size_t)(bn + _r) * DIM + _k + _g * 8;                    \
        CP16(_ab + _d,         g_xh + _go);                                    \
        CP16(_ab + 16384 + _d, g_wq + _wo);                                    \
        CP16(_ab + 32768 + _d, g_wk + _wo);                                    \
        CP16(_ab + 49152 + _d, g_wv + _wo);                                    \
    }                                                                          \
    CPC();                                                                     \
} while (0)

    Q3STAGE(0, 0);
    Q3STAGE(1, 1);

    for (int s = 0; s < 12; s++) {
        if (s + 1 < 12) CPW1(); else CPW0();
        __syncthreads();
        if (s + 2 < 12) Q3STAGE((s + 2) % 3, s + 2);

        uint32_t Ab = base + (s % 3) * 65536;
        #pragma unroll
        for (int kc = 0; kc < 4; kc++) {
            uint32_t a[4][4];
            #pragma unroll
            for (int mf = 0; mf < 4; mf++)
                LDSM4(a[mf][0], a[mf][1], a[mf][2], a[mf][3],
                      swad(Ab, arow + mf * 16, 2 * kc + achk));
            #pragma unroll
            for (int w = 0; w < 3; w++) {
                uint32_t b[2][4];
                uint32_t Bb = Ab + 16384 + w * 16384;
                #pragma unroll
                for (int n2 = 0; n2 < 2; n2++)
                    LDSM4(b[n2][0], b[n2][1], b[n2][2], b[n2][3],
                          swad(Bb, brow + n2 * 16, 2 * kc + bchk));
                #pragma unroll
                for (int mf = 0; mf < 4; mf++)
                    #pragma unroll
                    for (int nf = 0; nf < 4; nf++)
                        MMA_F16(acc[w][mf][nf],
                                a[mf][0], a[mf][1], a[mf][2], a[mf][3],
                                b[nf >> 1][(nf & 1) * 2], b[nf >> 1][(nf & 1) * 2 + 1]);
            }
        }
    }
#undef Q3STAGE

    #pragma unroll
    for (int w = 0; w < 3; w++) {
        __half* C = (w == 0) ? g_q : (w == 1) ? g_k : g_v;
        float osc = (w == 0) ? QSCALE : 1.0f;
        #pragma unroll
        for (int mf = 0; mf < 4; mf++) {
            int row = bm + wm * 64 + mf * 16 + gp;
            #pragma unroll
            for (int nf = 0; nf < 4; nf++) {
                int cc = bn + wn * 32 + nf * 8 + 2 * tg;
                *(__half2*)(C + (size_t)row * DIM + cc) =
                    __floats2half2_rn(acc[w][mf][nf].x * osc, acc[w][mf][nf].y * osc);
                *(__half2*)(C + (size_t)(row + 8) * DIM + cc) =
                    __floats2half2_rn(acc[w][mf][nf].z * osc, acc[w][mf][nf].w * osc);
            }
        }
    }
}

// ---------------------------------------------------------------------------
// Output projection (R12, proven): 128x128 CTA tile, 4 warps (2x2),
// warp 64x64, BK=64, 3-slot ring, 128 threads, 2 CTAs/SM. fp32 + bias.
// ---------------------------------------------------------------------------
__global__ void __launch_bounds__(128, 2) gemm_out(
    const float* __restrict__ bias, float* __restrict__ C)
{
    extern __shared__ uint32_t smw[];

    const int tid = threadIdx.x, lane = tid & 31, warp = tid >> 5;
    const int wm = warp >> 1, wn = warp & 1;
    const int tg = lane & 3, gp = lane >> 2;
    const int l8 = lane & 7, lg = lane >> 3;
    const int bm = blockIdx.y * 128, bn = blockIdx.x * 128;
    const uint32_t base = smem_u32(smw);

    float4 acc[4][8];
    #pragma unroll
    for (int i = 0; i < 4; i++)
        #pragma unroll
        for (int j = 0; j < 8; j++) acc[i][j] = make_float4(0.f, 0.f, 0.f, 0.f);

    const int arow = wm * 64 + l8 + ((lg & 1) << 3);
    const int achk = lg >> 1;
    const int brow = wn * 64 + l8 + ((lg >> 1) << 3);
    const int bchk = lg & 1;

#define OSTAGE(SLOT, S) do {                                                   \
    int _k = (S) * 64;                                                         \
    uint32_t _ab = base + (SLOT) * 32768;                                      \
    _Pragma("unroll")                                                          \
    for (int _u = tid; _u < 1024; _u += 128) {                                 \
        int _r = _u >> 3, _g = _u & 7;                                         \
        uint32_t _d = _r * 128 + ((_g ^ (_r & 7)) << 4);                       \
        CP16(_ab + _d,         g_o + (size_t)(bm + _r) * DIM + _k + _g * 8);   \
        CP16(_ab + 16384 + _d, g_wp + (size_t)(bn + _r) * DIM + _k + _g * 8);  \
    }                                                                          \
    CPC();                                                                     \
} while (0)

    OSTAGE(0, 0);
    OSTAGE(1, 1);

    for (int s = 0; s < 12; s++) {
        if (s + 1 < 12) CPW1(); else CPW0();
        __syncthreads();
        if (s + 2 < 12) OSTAGE((s + 2) % 3, s + 2);

        uint32_t Ab = base + (s % 3) * 32768;
        uint32_t Bb = Ab + 16384;
        #pragma unroll
        for (int kc = 0; kc < 4; kc++) {
            uint32_t a[4][4], b[4][4];
            #pragma unroll
            for (int mf = 0; mf < 4; mf++)
                LDSM4(a[mf][0], a[mf][1], a[mf][2], a[mf][3],
                      swad(Ab, arow + mf * 16, 2 * kc + achk));
            #pragma unroll
            for (int ng = 0; ng < 4; ng++)
                LDSM4(b[ng][0], b[ng][1], b[ng][2], b[ng][3],
                      swad(Bb, brow + ng * 16, 2 * kc + bchk));
            #pragma unroll
            for (int mf = 0; mf < 4; mf++)
                #pragma unroll
                for (int ng = 0; ng < 4; ng++) {
                    MMA_F16(acc[mf][2 * ng],     a[mf][0], a[mf][1], a[mf][2], a[mf][3],
                            b[ng][0], b[ng][1]);
                    MMA_F16(acc[mf][2 * ng + 1], a[mf][0], a[mf][1], a[mf][2], a[mf][3],
                            b[ng][2], b[ng][3]);
                }
        }
    }
#undef OSTAGE

    #pragma unroll
    for (int mf = 0; mf < 4; mf++) {
        int row = bm + wm * 64 + mf * 16 + gp;
        #pragma unroll
        for (int nf = 0; nf < 8; nf++) {
            int cc = bn + wn * 64 + nf * 8 + 2 * tg;
            float b0 = bias[cc], b1 = bias[cc + 1];
            *(float2*)(C + (size_t)row * DIM + cc) =
                make_float2(acc[mf][nf].x + b0, acc[mf][nf].y + b1);
            *(float2*)(C + (size_t)(row + 8) * DIM + cc) =
                make_float2(acc[mf][nf].z + b0, acc[mf][nf].w + b1);
        }
    }
}

// ---------------------------------------------------------------------------
// fp16 mma flash attention (R14, proven): 64 q-rows/CTA, 4 warps x 16 rows,
// persistent Q frags, KV tile 64, 3-slot cp.async ring, 4 CTAs/SM.
// Q prescaled by 0.125*log2e -> softmax p = ex2(s).
// ---------------------------------------------------------------------------
__global__ void __launch_bounds__(128, 4) flash_h()
{
    extern __shared__ uint32_t smw[];
    const uint32_t base = smem_u32(smw);
    const uint32_t Qb = base;

    const int tid = threadIdx.x, lane = tid & 31, warp = tid >> 5;
    const int tg = lane & 3, gp = lane >> 2;
    const int l8 = lane & 7, lg = lane >> 3;
    const int h = blockIdx.y, b = blockIdx.z, q0 = blockIdx.x * 64;

    const int arow = warp * 16 + l8 + ((lg & 1) << 3);
    const int achk = lg >> 1;
    const int brow = l8 + ((lg >> 1) << 3);
    const int bchk = lg & 1;
    const int vrow = l8 + ((lg & 1) << 3);
    const int vchk = lg >> 1;

    const __half* qg = g_q + (size_t)(b * SEQ + q0) * DIM + h * HD;
    #pragma unroll
    for (int u = tid; u < 512; u += 128) {
        int r = u >> 3, g = u & 7;
        CP16(Qb + r * 128 + ((g ^ (r & 7)) << 4), qg + (size_t)r * DIM + g * 8);
    }
    CPC();

#define KVSTAGE(SLOT, T) do {                                                  \
    const __half* _kg = g_k + (size_t)(b * SEQ + (T) * 64) * DIM + h * HD;     \
    const __half* _vg = g_v + (size_t)(b * SEQ + (T) * 64) * DIM + h * HD;     \
    uint32_t _kb = base + 8192 + (SLOT) * 8192;                                \
    uint32_t _vb = base + 32768 + (SLOT) * 8192;                               \
    _Pragma("unroll")                                                          \
    for (int _u = tid; _u < 512; _u += 128) {                                  \
        int _r = _u >> 3, _g = _u & 7;                                         \
        uint32_t _d = _r * 128 + ((_g ^ (_r & 7)) << 4);                       \
        CP16(_kb + _d, _kg + (size_t)_r * DIM + _g * 8);                       \
        CP16(_vb + _d, _vg + (size_t)_r * DIM + _g * 8);                       \
    }                                                                          \
    CPC();                                                                     \
} while (0)

    KVSTAGE(0, 0);
    KVSTAGE(1, 1);

    uint32_t qa[4][4];
    float4 oacc[8];
    float rs0 = 0.f, rs1 = 0.f;
    #pragma unroll
    for (int j = 0; j < 8; j++) oacc[j] = make_float4(0.f, 0.f, 0.f, 0.f);

    const int NT = SEQ / 64;
    for (int t = 0; t < NT; t++) {
        if (t + 1 < NT) CPW1(); else CPW0();
        __syncthreads();
        if (t + 2 < NT) KVSTAGE((t + 2) % 3, t + 2);

        if (t == 0) {
            #pragma unroll
            for (int kc = 0; kc < 4; kc++)
                LDSM4(qa[kc][0], qa[kc][1], qa[kc][2], qa[kc][3],
                      swad(Qb, arow, 2 * kc + achk));
        }

        uint32_t Kb = base + 8192 + (t % 3) * 8192;
        uint32_t Vb = base + 32768 + (t % 3) * 8192;

        float4 s[8];
        #pragma unroll
        for (int j = 0; j < 8; j++) s[j] = make_float4(0.f, 0.f, 0.f, 0.f);
        #pragma unroll
        for (int kc = 0; kc < 4; kc++) {
            uint32_t bb[4][4];
            #pragma unroll
            for (int ng = 0; ng < 4; ng++)
                LDSM4(bb[ng][0], bb[ng][1], bb[ng][2], bb[ng][3],
                      swad(Kb, ng * 16 + brow, 2 * kc + bchk));
            #pragma unroll
            for (int ng = 0; ng < 4; ng++) {
                MMA_F16(s[2 * ng],     qa[kc][0], qa[kc][1], qa[kc][2], qa[kc][3],
                        bb[ng][0], bb[ng][1]);
                MMA_F16(s[2 * ng + 1], qa[kc][0], qa[kc][1], qa[kc][2], qa[kc][3],
                        bb[ng][2], bb[ng][3]);
            }
        }

        uint32_t pa[8], pb[8];
        #pragma unroll
        for (int j = 0; j < 8; j++) {
            float px = ex2f(s[j].x);
            float py = ex2f(s[j].y);
            float pz = ex2f(s[j].z);
            float pw = ex2f(s[j].w);
            rs0 += px + py;
            rs1 += pz + pw;
            __half2 hA = __floats2half2_rn(px, py);
            __half2 hB = __floats2half2_rn(pz, pw);
            pa[j] = *(uint32_t*)&hA;
            pb[j] = *(uint32_t*)&hB;
        }

        #pragma unroll
        for (int kc = 0; kc < 4; kc++) {
            uint32_t vv[4][4];
            #pragma unroll
            for (int dg = 0; dg < 4; dg++)
                LDSM4T(vv[dg][0], vv[dg][1], vv[dg][2], vv[dg][3],
                       swad(Vb, kc * 16 + vrow, 2 * dg + vchk));
            #pragma unroll
            for (int dg = 0; dg < 4; dg++) {
                MMA_F16(oacc[2 * dg],     pa[2 * kc], pb[2 * kc],
                        pa[2 * kc + 1], pb[2 * kc + 1], vv[dg][0], vv[dg][1]);
                MMA_F16(oacc[2 * dg + 1], pa[2 * kc], pb[2 * kc],
                        pa[2 * kc + 1], pb[2 * kc + 1], vv[dg][2], vv[dg][3]);
            }
        }
    }
#undef KVSTAGE

    rs0 += __shfl_xor_sync(0xffffffffu, rs0, 1, 4);
    rs0 += __shfl_xor_sync(0xffffffffu, rs0, 2, 4);
    rs1 += __shfl_xor_sync(0xffffffffu, rs1, 1, 4);
    rs1 += __shfl_xor_sync(0xffffffffu, rs1, 2, 4);
    float i0 = 1.0f / rs0, i1 = 1.0f / rs1;

    __half* og = g_o + (size_t)(b * SEQ + q0 + warp * 16) * DIM + h * HD;
    #pragma unroll
    for (int j = 0; j < 8; j++) {
        int cc = 8 * j + 2 * tg;
        *(__half2*)(og + (size_t)gp * DIM + cc) =
            __floats2half2_rn(oacc[j].x * i0, oacc[j].y * i0);
        *(__half2*)(og + (size_t)(gp + 8) * DIM + cc) =
            __floats2half2_rn(oacc[j].z * i1, oacc[j].w * i1);
    }
}

// ---------------------------------------------------------------------------
extern "C" void kernel_launch(void* const* d_in, const int* in_sizes, int n_in,
                              void* d_out, int out_size)
{
    const float* x  = (const float*)d_in[0];
    const float* Wq = (const float*)d_in[1];
    const float* Wk = (const float*)d_in[2];
    const float* Wv = (const float*)d_in[3];
    const float* Wp = (const float*)d_in[4];
    const float* bp = (const float*)d_in[5];
    float* out = (float*)d_out;

    const int qkv3_smem  = 196608;  // 3 x 64KB
    const int out_smem   = 98304;   // 3 x 32KB
    const int flash_smem = 57344;   // Q 8KB + 3x(K 8KB + V 8KB)
    cudaFuncSetAttribute(gemm_qkv3, cudaFuncAttributeMaxDynamicSharedMemorySize, qkv3_smem);
    cudaFuncSetAttribute(gemm_out,  cudaFuncAttributeMaxDynamicSharedMemorySize, out_smem);
    cudaFuncSetAttribute(flash_h,   cudaFuncAttributeMaxDynamicSharedMemorySize, flash_smem);

    cvt_half<<<1024, 256>>>(x, Wq, Wk, Wv, Wp);

    dim3 gQ3(DIM / 128, M_TOTAL / 128);       // (6, 64) = 384 CTAs, triple-output
    gemm_qkv3<<<gQ3, 256, qkv3_smem>>>();

    dim3 gF(SEQ / 64, HEADS, BATCH);          // (32, 12, 4)
    flash_h<<<gF, 128, flash_smem>>>();

    dim3 gO(DIM / 128, M_TOTAL / 128);        // (6, 64)
    gemm_out<<<gO, 128, out_smem>>>(bp, out);
}

// round 16
// speedup vs baseline: 1.1362x; 1.1362x over previous
#include <cuda_runtime.h>
#include <cuda_fp16.h>
#include <cstdint>

#define DIM     768
#define HEADS   12
#define HD      64
#define BATCH   4
#define SEQ     2048
#define M_TOTAL (BATCH * SEQ)

// Q prescale: 0.125 (attn scale) * log2(e), folded into Q so softmax is bare ex2
#define QSCALE  0.18033688011112042f

// Scratch (static device globals: allocation-guard safe)
__device__ __half g_xh[M_TOTAL * DIM];
__device__ __half g_wq[DIM * DIM], g_wk[DIM * DIM], g_wv[DIM * DIM], g_wp[DIM * DIM];
__device__ __half g_q[M_TOTAL * DIM], g_k[M_TOTAL * DIM];
__device__ __half g_v[M_TOTAL * DIM], g_o[M_TOTAL * DIM];

__device__ __forceinline__ uint32_t smem_u32(const void* p) {
    uint32_t a;
    asm("{ .reg .u64 t; cvta.to.shared.u64 t, %1; cvt.u32.u64 %0, t; }"
        : "=r"(a) : "l"(p));
    return a;
}
__device__ __forceinline__ float ex2f(float x) {
    float r;
    asm("ex2.approx.f32 %0, %1;" : "=f"(r) : "f"(x));
    return r;
}

#define CP16(dst, src) \
    asm volatile("cp.async.cg.shared.global [%0], [%1], 16;\n" :: "r"(dst), "l"(src))
#define CPC()  asm volatile("cp.async.commit_group;\n" ::: "memory")
#define CPW2() asm volatile("cp.async.wait_group 2;\n" ::: "memory")
#define CPW1() asm volatile("cp.async.wait_group 1;\n" ::: "memory")
#define CPW0() asm volatile("cp.async.wait_group 0;\n" ::: "memory")

#define LDSM4(r0, r1, r2, r3, a)                                              \
    asm volatile("ldmatrix.sync.aligned.m8n8.x4.shared.b16 {%0,%1,%2,%3}, [%4];" \
        : "=r"(r0), "=r"(r1), "=r"(r2), "=r"(r3) : "r"(a))
#define LDSM4T(r0, r1, r2, r3, a)                                             \
    asm volatile("ldmatrix.sync.aligned.m8n8.x4.trans.shared.b16 {%0,%1,%2,%3}, [%4];" \
        : "=r"(r0), "=r"(r1), "=r"(r2), "=r"(r3) : "r"(a))

// D += A(16x16,row) * B(16x8,col) — fp16 inputs, fp32 accum
#define MMA_F16(d, a0, a1, a2, a3, b0, b1)                                    \
    asm volatile("mma.sync.aligned.m16n8k16.row.col.f32.f16.f16.f32 "         \
        "{%0,%1,%2,%3}, {%4,%5,%6,%7}, {%8,%9}, {%0,%1,%2,%3};"               \
        : "+f"((d).x), "+f"((d).y), "+f"((d).z), "+f"((d).w)                  \
        : "r"(a0), "r"(a1), "r"(a2), "r"(a3), "r"(b0), "r"(b1))

// Swizzled byte address: 128B rows, 8 chunks of 16B, chunk key = row&7
__device__ __forceinline__ uint32_t swad(uint32_t base, int row, int chk) {
    return base + row * 128 + ((chk ^ (row & 7)) << 4);
}

// ---------------------------------------------------------------------------
// fp32 -> fp16 conversion: 32B of halves per thread-iter (uint4 stores)
// ---------------------------------------------------------------------------
__global__ void cvt_half(const float* __restrict__ x,  const float* __restrict__ wq,
                         const float* __restrict__ wk, const float* __restrict__ wv,
                         const float* __restrict__ wp)
{
    const int NX = M_TOTAL * DIM / 8;
    const int NW = DIM * DIM / 8;
    int stride = gridDim.x * blockDim.x;
    for (int u = blockIdx.x * blockDim.x + threadIdx.x; u < NX + 4 * NW; u += stride) {
        const float* src; __half* dst; int off;
        if (u < NX) { src = x; dst = g_xh; off = u; }
        else {
            int w = (u - NX) / NW, r = (u - NX) % NW;
            src = (w == 0) ? wq : (w == 1) ? wk : (w == 2) ? wv : wp;
            dst = (w == 0) ? g_wq : (w == 1) ? g_wk : (w == 2) ? g_wv : g_wp;
            off = r;
        }
        float4 f0 = ((const float4*)src)[off * 2 + 0];
        float4 f1 = ((const float4*)src)[off * 2 + 1];
        __half2 h[4];
        h[0] = __floats2half2_rn(f0.x, f0.y);
        h[1] = __floats2half2_rn(f0.z, f0.w);
        h[2] = __floats2half2_rn(f1.x, f1.y);
        h[3] = __floats2half2_rn(f1.z, f1.w);
        ((uint4*)dst)[off] = *(uint4*)h;
    }
}

// ---------------------------------------------------------------------------
// fp16 mma GEMM (R12/R14, proven): 128x128 CTA tile, 4 warps (2x2),
// warp 64x64, BK=64, 3-slot cp.async ring, 128 threads, 2 CTAs/SM.
// MODE 0: half out (Q prescaled when QKV && z==0). MODE 1: fp32 + bias.
// ---------------------------------------------------------------------------
template <int MODE, int QKV>
__global__ void __launch_bounds__(128, 2) gemm_h(
    const __half* __restrict__ A,
    const __half* __restrict__ W0, const __half* __restrict__ W1,
    const __half* __restrict__ W2,
    const float* __restrict__ bias,
    void* __restrict__ C0, void* __restrict__ C1, void* __restrict__ C2)
{
    extern __shared__ uint32_t smw[];

    const __half* W = W0;
    void* Cv = C0;
    float osc = 1.0f;
    if (QKV) {
        if (blockIdx.z == 1) { W = W1; Cv = C1; }
        else if (blockIdx.z == 2) { W = W2; Cv = C2; }
        else osc = QSCALE;
    }

    const int tid = threadIdx.x, lane = tid & 31, warp = tid >> 5;
    const int wm = warp >> 1, wn = warp & 1;
    const int tg = lane & 3, gp = lane >> 2;
    const int l8 = lane & 7, lg = lane >> 3;
    const int bm = blockIdx.y * 128, bn = blockIdx.x * 128;
    const uint32_t base = smem_u32(smw);

    float4 acc[4][8];
    #pragma unroll
    for (int i = 0; i < 4; i++)
        #pragma unroll
        for (int j = 0; j < 8; j++) acc[i][j] = make_float4(0.f, 0.f, 0.f, 0.f);

    const int arow = wm * 64 + l8 + ((lg & 1) << 3);
    const int achk = lg >> 1;
    const int brow = wn * 64 + l8 + ((lg >> 1) << 3);
    const int bchk = lg & 1;

#define GSTAGE(SLOT, S) do {                                                   \
    int _k = (S) * 64;                                                         \
    uint32_t _ab = base + (SLOT) * 32768;                                      \
    _Pragma("unroll")                                                          \
    for (int _u = tid; _u < 1024; _u += 128) {                                 \
        int _r = _u >> 3, _g = _u & 7;                                         \
        uint32_t _d = _r * 128 + ((_g ^ (_r & 7)) << 4);                       \
        CP16(_ab + _d,         A + (size_t)(bm + _r) * DIM + _k + _g * 8);     \
        CP16(_ab + 16384 + _d, W + (size_t)(bn + _r) * DIM + _k + _g * 8);     \
    }                                                                          \
    CPC();                                                                     \
} while (0)

    GSTAGE(0, 0);
    GSTAGE(1, 1);

    for (int s = 0; s < 12; s++) {
        if (s + 1 < 12) CPW1(); else CPW0();
        __syncthreads();
        if (s + 2 < 12) GSTAGE((s + 2) % 3, s + 2);

        uint32_t Ab = base + (s % 3) * 32768;
        uint32_t Bb = Ab + 16384;
        #pragma unroll
        for (int kc = 0; kc < 4; kc++) {
            uint32_t a[4][4], b[4][4];
            #pragma unroll
            for (int mf = 0; mf < 4; mf++)
                LDSM4(a[mf][0], a[mf][1], a[mf][2], a[mf][3],
                      swad(Ab, arow + mf * 16, 2 * kc + achk));
            #pragma unroll
            for (int ng = 0; ng < 4; ng++)
                LDSM4(b[ng][0], b[ng][1], b[ng][2], b[ng][3],
                      swad(Bb, brow + ng * 16, 2 * kc + bchk));
            #pragma unroll
            for (int mf = 0; mf < 4; mf++)
                #pragma unroll
                for (int ng = 0; ng < 4; ng++) {
                    MMA_F16(acc[mf][2 * ng],     a[mf][0], a[mf][1], a[mf][2], a[mf][3],
                            b[ng][0], b[ng][1]);
                    MMA_F16(acc[mf][2 * ng + 1], a[mf][0], a[mf][1], a[mf][2], a[mf][3],
                            b[ng][2], b[ng][3]);
                }
        }
    }
#undef GSTAGE

    #pragma unroll
    for (int mf = 0; mf < 4; mf++) {
        int row = bm + wm * 64 + mf * 16 + gp;
        #pragma unroll
        for (int nf = 0; nf < 8; nf++) {
            int cc = bn + wn * 64 + nf * 8 + 2 * tg;
            if (MODE == 0) {
                __half* C = (__half*)Cv;
                *(__half2*)(C + (size_t)row * DIM + cc) =
                    __floats2half2_rn(acc[mf][nf].x * osc, acc[mf][nf].y * osc);
                *(__half2*)(C + (size_t)(row + 8) * DIM + cc) =
                    __floats2half2_rn(acc[mf][nf].z * osc, acc[mf][nf].w * osc);
            } else {
                float* C = (float*)Cv;
                float b0 = bias[cc], b1 = bias[cc + 1];
                *(float2*)(C + (size_t)row * DIM + cc) =
                    make_float2(acc[mf][nf].x + b0, acc[mf][nf].y + b1);
                *(float2*)(C + (size_t)(row + 8) * DIM + cc) =
                    make_float2(acc[mf][nf].z + b0, acc[mf][nf].w + b1);
            }
        }
    }
}

// ---------------------------------------------------------------------------
// fp16 mma flash attention (R14, proven): 64 q-rows/CTA, 4 warps x 16 rows,
// persistent Q frags (hoisted pre-loop via wait_group 2), KV tile 64,
// 3-slot cp.async ring, 4 CTAs/SM. Q prescaled -> softmax p = ex2(s).
// ---------------------------------------------------------------------------
__global__ void __launch_bounds__(128, 4) flash_h(
    const __half* __restrict__ q, const __half* __restrict__ k,
    const __half* __restrict__ v, __half* __restrict__ o)
{
    extern __shared__ uint32_t smw[];
    const uint32_t base = smem_u32(smw);
    const uint32_t Qb = base;

    const int tid = threadIdx.x, lane = tid & 31, warp = tid >> 5;
    const int tg = lane & 3, gp = lane >> 2;
    const int l8 = lane & 7, lg = lane >> 3;
    const int h = blockIdx.y, b = blockIdx.z, q0 = blockIdx.x * 64;

    const int arow = warp * 16 + l8 + ((lg & 1) << 3);
    const int achk = lg >> 1;
    const int brow = l8 + ((lg >> 1) << 3);
    const int bchk = lg & 1;
    const int vrow = l8 + ((lg & 1) << 3);
    const int vchk = lg >> 1;

    // Q tile (cp.async group 0)
    const __half* qg = q + (size_t)(b * SEQ + q0) * DIM + h * HD;
    #pragma unroll
    for (int u = tid; u < 512; u += 128) {
        int r = u >> 3, g = u & 7;
        CP16(Qb + r * 128 + ((g ^ (r & 7)) << 4), qg + (size_t)r * DIM + g * 8);
    }
    CPC();

#define KVSTAGE(SLOT, T) do {                                                  \
    const __half* _kg = k + (size_t)(b * SEQ + (T) * 64) * DIM + h * HD;       \
    const __half* _vg = v + (size_t)(b * SEQ + (T) * 64) * DIM + h * HD;       \
    uint32_t _kb = base + 8192 + (SLOT) * 8192;                                \
    uint32_t _vb = base + 32768 + (SLOT) * 8192;                               \
    _Pragma("unroll")                                                          \
    for (int _u = tid; _u < 512; _u += 128) {                                  \
        int _r = _u >> 3, _g = _u & 7;                                         \
        uint32_t _d = _r * 128 + ((_g ^ (_r & 7)) << 4);                       \
        CP16(_kb + _d, _kg + (size_t)_r * DIM + _g * 8);                       \
        CP16(_vb + _d, _vg + (size_t)_r * DIM + _g * 8);                       \
    }                                                                          \
    CPC();                                                                     \
} while (0)

    KVSTAGE(0, 0);
    KVSTAGE(1, 1);

    // Hoisted one-time Q fragment load: wait for group 0 (Q) only
    // (2 KV groups may remain in flight), no block barrier needed —
    // each warp reads only Q rows it wrote? (no: Q written cooperatively)
    // -> a barrier IS required before reading Q. Use wait 2 + sync once.
    CPW2();
    __syncthreads();
    uint32_t qa[4][4];
    #pragma unroll
    for (int kc = 0; kc < 4; kc++)
        LDSM4(qa[kc][0], qa[kc][1], qa[kc][2], qa[kc][3],
              swad(Qb, arow, 2 * kc + achk));

    float4 oacc[8];
    float rs0 = 0.f, rs1 = 0.f;
    #pragma unroll
    for (int j = 0; j < 8; j++) oacc[j] = make_float4(0.f, 0.f, 0.f, 0.f);

    const int NT = SEQ / 64;
    for (int t = 0; t < NT; t++) {
        if (t + 1 < NT) CPW1(); else CPW0();
        __syncthreads();
        if (t + 2 < NT) KVSTAGE((t + 2) % 3, t + 2);

        uint32_t Kb = base + 8192 + (t % 3) * 8192;
        uint32_t Vb = base + 32768 + (t % 3) * 8192;

        // ---- S = Q~ @ K^T : 16 x 64 per warp ----
        float4 s[8];
        #pragma unroll
        for (int j = 0; j < 8; j++) s[j] = make_float4(0.f, 0.f, 0.f, 0.f);
        #pragma unroll
        for (int kc = 0; kc < 4; kc++) {
            uint32_t bb[4][4];
            #pragma unroll
            for (int ng = 0; ng < 4; ng++)
                LDSM4(bb[ng][0], bb[ng][1], bb[ng][2], bb[ng][3],
                      swad(Kb, ng * 16 + brow, 2 * kc + bchk));
            #pragma unroll
            for (int ng = 0; ng < 4; ng++) {
                MMA_F16(s[2 * ng],     qa[kc][0], qa[kc][1], qa[kc][2], qa[kc][3],
                        bb[ng][0], bb[ng][1]);
                MMA_F16(s[2 * ng + 1], qa[kc][0], qa[kc][1], qa[kc][2], qa[kc][3],
                        bb[ng][2], bb[ng][3]);
            }
        }

        // ---- softmax: p = ex2(s); pack as PV A-fragments ----
        uint32_t pa[8], pb[8];
        #pragma unroll
        for (int j = 0; j < 8; j++) {
            float px = ex2f(s[j].x);
            float py = ex2f(s[j].y);
            float pz = ex2f(s[j].z);
            float pw = ex2f(s[j].w);
            rs0 += px + py;
            rs1 += pz + pw;
            __half2 hA = __floats2half2_rn(px, py);
            __half2 hB = __floats2half2_rn(pz, pw);
            pa[j] = *(uint32_t*)&hA;
            pb[j] = *(uint32_t*)&hB;
        }

        // ---- O += P @ V : P from registers, V via ldmatrix.trans ----
        #pragma unroll
        for (int kc = 0; kc < 4; kc++) {
            uint32_t vv[4][4];
            #pragma unroll
            for (int dg = 0; dg < 4; dg++)
                LDSM4T(vv[dg][0], vv[dg][1], vv[dg][2], vv[dg][3],
                       swad(Vb, kc * 16 + vrow, 2 * dg + vchk));
            #pragma unroll
            for (int dg = 0; dg < 4; dg++) {
                MMA_F16(oacc[2 * dg],     pa[2 * kc], pb[2 * kc],
                        pa[2 * kc + 1], pb[2 * kc + 1], vv[dg][0], vv[dg][1]);
                MMA_F16(oacc[2 * dg + 1], pa[2 * kc], pb[2 * kc],
                        pa[2 * kc + 1], pb[2 * kc + 1], vv[dg][2], vv[dg][3]);
            }
        }
    }
#undef KVSTAGE

    rs0 += __shfl_xor_sync(0xffffffffu, rs0, 1, 4);
    rs0 += __shfl_xor_sync(0xffffffffu, rs0, 2, 4);
    rs1 += __shfl_xor_sync(0xffffffffu, rs1, 1, 4);
    rs1 += __shfl_xor_sync(0xffffffffu, rs1, 2, 4);
    float i0 = 1.0f / rs0, i1 = 1.0f / rs1;

    __half* og = o + (size_t)(b * SEQ + q0 + warp * 16) * DIM + h * HD;
    #pragma unroll
    for (int j = 0; j < 8; j++) {
        int cc = 8 * j + 2 * tg;
        *(__half2*)(og + (size_t)gp * DIM + cc) =
            __floats2half2_rn(oacc[j].x * i0, oacc[j].y * i0);
        *(__half2*)(og + (size_t)(gp + 8) * DIM + cc) =
            __floats2half2_rn(oacc[j].z * i1, oacc[j].w * i1);
    }
}

// ---------------------------------------------------------------------------
extern "C" void kernel_launch(void* const* d_in, const int* in_sizes, int n_in,
                              void* d_out, int out_size)
{
    const float* x  = (const float*)d_in[0];
    const float* Wq = (const float*)d_in[1];
    const float* Wk = (const float*)d_in[2];
    const float* Wv = (const float*)d_in[3];
    const float* Wp = (const float*)d_in[4];
    const float* bp = (const float*)d_in[5];
    float* out = (float*)d_out;

    __half *xh, *wq, *wk, *wv, *wp, *qh, *kh, *vh, *oh;
    cudaGetSymbolAddress((void**)&xh, g_xh);
    cudaGetSymbolAddress((void**)&wq, g_wq);
    cudaGetSymbolAddress((void**)&wk, g_wk);
    cudaGetSymbolAddress((void**)&wv, g_wv);
    cudaGetSymbolAddress((void**)&wp, g_wp);
    cudaGetSymbolAddress((void**)&qh, g_q);
    cudaGetSymbolAddress((void**)&kh, g_k);
    cudaGetSymbolAddress((void**)&vh, g_v);
    cudaGetSymbolAddress((void**)&oh, g_o);

    const int gemm_smem  = 98304;   // 3 x 32KB
    const int flash_smem = 57344;   // Q 8KB + 3x(K 8KB + V 8KB)
    cudaFuncSetAttribute(gemm_h<0, 1>, cudaFuncAttributeMaxDynamicSharedMemorySize, gemm_smem);
    cudaFuncSetAttribute(gemm_h<1, 0>, cudaFuncAttributeMaxDynamicSharedMemorySize, gemm_smem);
    cudaFuncSetAttribute(flash_h, cudaFuncAttributeMaxDynamicSharedMemorySize, flash_smem);

    cvt_half<<<2048, 256>>>(x, Wq, Wk, Wv, Wp);

    dim3 gQKV(DIM / 128, M_TOTAL / 128, 3);   // (6, 64, 3)
    gemm_h<0, 1><<<gQKV, 128, gemm_smem>>>(xh, wq, wk, wv, nullptr, qh, kh, vh);

    dim3 gF(SEQ / 64, HEADS, BATCH);          // (32, 12, 4) = 1536 CTAs
    flash_h<<<gF, 128, flash_smem>>>(qh, kh, vh, oh);

    dim3 gG(DIM / 128, M_TOTAL / 128);        // (6, 64)
    gemm_h<1, 0><<<gG, 128, gemm_smem>>>(oh, wp, nullptr, nullptr, bp, out, nullptr, nullptr);
}